// round 11
// baseline (speedup 1.0000x reference)
#include <cuda_runtime.h>
#include <stdint.h>

// Ragged gather, 4 tokens/thread (verified wiring from R8 recon):
//   in0 = req_to_token [4096 x 32768] int32
//   in1 = req_pool_indices [64], in2 = chunk_starts [64],
//   in3 = chunk_seq_lens [64] (unused), in4 = chunk_cu_seq_lens [65]
// Output dtype float32 (verified R10):
//   out[t] = (float) table[pool[seg]*32768 + starts[seg] + (t - cu[seg])]
// One binary search per thread for its first token; consecutive tokens advance
// seg with a cheap smem walk. 4 independent LDGs per thread (MLP=4), float4 store.

#define BMAX 64

__global__ __launch_bounds__(256)
void ragged_gather_x4(
    const int* __restrict__ table,
    const int* __restrict__ pool,
    const int* __restrict__ starts,
    const int* __restrict__ cu,
    float* __restrict__ out,
    int T, int batch, int cols, int rows)
{
    __shared__ int s_cu[BMAX + 1];
    __shared__ int s_row[BMAX];
    __shared__ int s_start[BMAX];

    const int tid = threadIdx.x;
    if (tid <= batch) s_cu[tid] = cu[tid];
    if (tid < batch) {
        s_row[tid]   = pool[tid];
        s_start[tid] = starts[tid];
    }
    __syncthreads();

    const int t0 = (blockIdx.x * blockDim.x + tid) * 4;
    if (t0 >= T) return;

    // Binary search: largest seg with s_cu[seg] <= t0
    int lo = 0, hi = batch - 1;
    while (lo < hi) {
        int mid = (lo + hi + 1) >> 1;
        if (s_cu[mid] <= t0) lo = mid; else hi = mid - 1;
    }
    int seg = lo;

    // Compute 4 gather indices (consecutive tokens; seg is non-decreasing).
    long long idx[4];
    int nv = 0;
    #pragma unroll
    for (int k = 0; k < 4; k++) {
        int t = t0 + k;
        if (t >= T) break;
        while (seg < batch - 1 && t >= s_cu[seg + 1]) seg++;
        int row = s_row[seg];
        int col = s_start[seg] + (t - s_cu[seg]);
        if (row < 0) row = 0; else if (row >= rows) row = rows - 1;
        if (col < 0) col = 0; else if (col >= cols) col = cols - 1;
        idx[k] = (long long)row * cols + col;
        nv = k + 1;
    }

    if (nv == 4) {
        // 4 independent loads issue back-to-back (MLP=4), then one 16B store.
        int v0 = __ldg(table + idx[0]);
        int v1 = __ldg(table + idx[1]);
        int v2 = __ldg(table + idx[2]);
        int v3 = __ldg(table + idx[3]);
        float4 o = make_float4((float)v0, (float)v1, (float)v2, (float)v3);
        *reinterpret_cast<float4*>(out + t0) = o;   // t0 % 4 == 0 -> 16B aligned
    } else {
        for (int k = 0; k < nv; k++)
            out[t0 + k] = (float)__ldg(table + idx[k]);
    }
}

extern "C" void kernel_launch(void* const* d_in, const int* in_sizes, int n_in,
                              void* d_out, int out_size)
{
    const int* table  = (const int*)d_in[0];
    const int* pool   = (const int*)d_in[1];
    const int* starts = (const int*)d_in[2];
    const int* cu     = (const int*)d_in[4];

    int batch = in_sizes[1];
    if (batch > BMAX) batch = BMAX;

    const int rows = 4096;                 // POOL_SIZE (verified)
    const int cols = in_sizes[0] / rows;   // 32768

    const int T = out_size;
    if (T <= 0) return;

    const int threads = 256;
    const int tokens_per_block = threads * 4;
    const int blocks = (T + tokens_per_block - 1) / tokens_per_block;
    ragged_gather_x4<<<blocks, threads>>>(
        table, pool, starts, cu, (float*)d_out, T, batch, cols, rows);
}

// round 12
// speedup vs baseline: 1.1140x; 1.1140x over previous
#include <cuda_runtime.h>
#include <stdint.h>

// Ragged gather, 1 token/thread (R10 shape — best so far), chain-shortened:
//   in0 = req_to_token [4096 x 32768] int32
//   in1 = req_pool_indices [64], in2 = chunk_starts [64],
//   in3 = chunk_seq_lens [64] (unused), in4 = chunk_cu_seq_lens [65]
//   out[t] = (float) table[ base[seg] + t ],  base[i] = pool[i]*cols + starts[i] - cu[i]
// Search is a branchless 6-step binary descent over s_cu; gather index needs
// only ONE post-search LDS (s_base) + IADD.

#define BMAX 64

__global__ __launch_bounds__(256)
void ragged_gather_fused(
    const int* __restrict__ table,
    const int* __restrict__ pool,
    const int* __restrict__ starts,
    const int* __restrict__ cu,
    float* __restrict__ out,
    int T, int batch, int cols, long long nelem)
{
    __shared__ int s_cu[BMAX + 1];
    __shared__ int s_base[BMAX];

    const int tid = threadIdx.x;
    if (tid < batch) {
        // Three independent LDGs -> one memory trip; fuse into base.
        int c = cu[tid];
        s_cu[tid]   = c;
        s_base[tid] = pool[tid] * cols + starts[tid] - c;
    }
    if (tid == batch) s_cu[batch] = cu[batch];
    __syncthreads();

    const int t = blockIdx.x * blockDim.x + tid;
    if (t >= T) return;

    // Branchless binary descent: largest seg with s_cu[seg] <= t.
    int seg = 0;
    #pragma unroll
    for (int step = 32; step > 0; step >>= 1) {
        int cand = seg + step;
        if (cand < batch && s_cu[cand] <= t) seg = cand;
    }

    long long idx = (long long)s_base[seg] + t;
    // Single safety clamp (a fault would kill the launch).
    if (idx < 0) idx = 0; else if (idx >= nelem) idx = nelem - 1;

    out[t] = (float)__ldg(table + idx);
}

extern "C" void kernel_launch(void* const* d_in, const int* in_sizes, int n_in,
                              void* d_out, int out_size)
{
    const int* table  = (const int*)d_in[0];
    const int* pool   = (const int*)d_in[1];
    const int* starts = (const int*)d_in[2];
    const int* cu     = (const int*)d_in[4];

    int batch = in_sizes[1];
    if (batch > BMAX) batch = BMAX;

    const int rows = 4096;                  // POOL_SIZE (verified)
    const int cols = in_sizes[0] / rows;    // 32768
    const long long nelem = (long long)in_sizes[0];

    const int T = out_size;
    if (T <= 0) return;

    const int threads = 256;
    const int blocks = (T + threads - 1) / threads;
    ragged_gather_fused<<<blocks, threads>>>(
        table, pool, starts, cu, (float*)d_out, T, batch, cols, nelem);
}